// round 15
// baseline (speedup 1.0000x reference)
#include <cuda_runtime.h>
#include <cuda_fp16.h>
#include <cstdint>

// ---------------------------------------------------------------------------
// MovePredictor: logits = W3 . relu(W2 . relu(W1.[e_src;e_tgt] + b1) + b2) + b3
//  - PQ = emb @ [W1_left; W1_right]^T over NODES (b1 folded into P), fp16 out
//  - pq consumes emb fp32 directly; h1 built on the fly in l23
//  - 1-pass fp16 GEMMs; 256-thread CTAs, 3 CTAs/SM (24 warps),
//    CTA tile 32x256, warp tile 32x32, BK=32, 2-stage cp.async,
//    one barrier per chunk.
// ---------------------------------------------------------------------------

#define N_NODES_MAX 100000
#define EMB_D   256
#define H1DIM   512
#define H2DIM   256
#define PQN     1024

#define BM 32
#define BN 256
#define BK 32
#define RS 80                    // 64B data + 16B pad
#define NT 256

// stage layout: A (32x80) + B hi (256x80)
#define A_O   0
#define BH_O  2560
#define STG   23040
#define AUXO  (STG * 2)          // 46080
#define SMEM_TOTAL (AUXO + 4096)

// ---- device globals (allocation-free scratch) ----
__device__ __half g_PQh[(size_t)N_NODES_MAX * PQN];
__device__ __half g_W1sh[(size_t)PQN * EMB_D];
__device__ __half g_W2h[(size_t)H2DIM * H1DIM];

// ---------------- helpers ----------------
__device__ __forceinline__ uint32_t smem_u32(const void* p) {
    uint32_t a;
    asm("{ .reg .u64 t; cvta.to.shared.u64 t, %1; cvt.u32.u64 %0, t; }"
        : "=r"(a) : "l"(p));
    return a;
}
__device__ __forceinline__ void cp16(uint32_t dst, const void* src) {
    asm volatile("cp.async.cg.shared.global [%0], [%1], 16;" :: "r"(dst), "l"(src));
}
__device__ __forceinline__ void cp_commit() {
    asm volatile("cp.async.commit_group;" ::: "memory");
}
__device__ __forceinline__ void cp_wait0() {
    asm volatile("cp.async.wait_group 0;" ::: "memory");
}
__device__ __forceinline__ void ldsm_x4(uint32_t* r, uint32_t addr) {
    asm volatile("ldmatrix.sync.aligned.m8n8.x4.shared.b16 {%0,%1,%2,%3}, [%4];"
                 : "=r"(r[0]), "=r"(r[1]), "=r"(r[2]), "=r"(r[3]) : "r"(addr));
}
__device__ __forceinline__ void mma_f16(float* c, const uint32_t* a,
                                        uint32_t b0, uint32_t b1) {
    asm volatile(
        "mma.sync.aligned.m16n8k16.row.col.f32.f16.f16.f32 "
        "{%0,%1,%2,%3}, {%4,%5,%6,%7}, {%8,%9}, {%0,%1,%2,%3};"
        : "+f"(c[0]), "+f"(c[1]), "+f"(c[2]), "+f"(c[3])
        : "r"(a[0]), "r"(a[1]), "r"(a[2]), "r"(a[3]), "r"(b0), "r"(b1));
}

// 32x32 warp tile over one 32-k chunk (2 k16 steps), 1-pass
__device__ __forceinline__ void mma_chunk1(uint32_t stg, int lane, int warp_n,
                                           float acc[2][4][4]) {
    const uint32_t aB = stg + A_O  + (lane & 15) * RS + (lane >> 4) * 16;
    const uint32_t bB = stg + BH_O + (warp_n * 32 + (lane & 15)) * RS + (lane >> 4) * 16;
    #pragma unroll
    for (int kt = 0; kt < 2; kt++) {
        uint32_t aR[2][4], bH[2][4];
        ldsm_x4(aR[0], aB + kt * 32);
        ldsm_x4(aR[1], aB + 16 * RS + kt * 32);
        ldsm_x4(bH[0], bB + kt * 32);
        ldsm_x4(bH[1], bB + 16 * RS + kt * 32);
        #pragma unroll
        for (int mt = 0; mt < 2; mt++)
            #pragma unroll
            for (int nb = 0; nb < 2; nb++) {
                mma_f16(acc[mt][2 * nb],     aR[mt], bH[nb][0], bH[nb][2]);
                mma_f16(acc[mt][2 * nb + 1], aR[mt], bH[nb][1], bH[nb][3]);
            }
    }
}

// ---------------- prep: weights only ----------------
__global__ void prep_w(const float* __restrict__ W1, const float* __restrict__ W2)
{
    int total = PQN * EMB_D + H2DIM * H1DIM;     // 393216
    for (int i = blockIdx.x * blockDim.x + threadIdx.x; i < total;
         i += gridDim.x * blockDim.x) {
        if (i < PQN * EMB_D) {
            int r = i >> 8, k = i & 255;
            g_W1sh[i] = __float2half_rn(
                W1[(size_t)(r & 511) * 512 + k + ((r >> 9) << 8)]);
        } else {
            int j = i - PQN * EMB_D;
            g_W2h[j] = __float2half_rn(W2[j]);
        }
    }
}

// ---------------- GEMM 1: PQ = emb @ W1s^T (+b1 on P half), fp16 out ----------------
__global__ __launch_bounds__(NT, 3)
void gemm_pq(const float* __restrict__ emb, const float* __restrict__ b1,
             int n_nodes)
{
    extern __shared__ char sm[];
    const uint32_t sb = smem_u32(sm);
    const int t = threadIdx.x, lane = t & 31, warp_n = t >> 5;
    const int m0 = blockIdx.y * BM;
    const int n0 = blockIdx.x * BN;

    float acc[2][4][4];
    #pragma unroll
    for (int a = 0; a < 2; a++)
        #pragma unroll
        for (int b = 0; b < 4; b++)
            #pragma unroll
            for (int c = 0; c < 4; c++) acc[a][b][c] = 0.f;

    // A path: 32 rows x 8 col-groups; per-thread 4 fp32 LDG -> cvt -> 8B STS
    const int ar = t >> 3;           // A row (0..31)
    const int aq = t & 7;            // 4-col group of 32
    int gm = m0 + ar; if (gm >= n_nodes) gm = n_nodes - 1;
    const float* embRow = emb + (size_t)gm * EMB_D + aq * 4;

    auto issueB = [&](int stage, int ch) {
        uint32_t sg = sb + stage * STG;
        int k0 = ch * BK;
        #pragma unroll
        for (int i = 0; i < 4; i++) {        // B hi: 1024 cp16
            int g = t + i * NT;
            int row = g >> 2, c = g & 3;
            cp16(sg + BH_O + row * RS + c * 16,
                 g_W1sh + (size_t)(n0 + row) * EMB_D + k0 + c * 8);
        }
        cp_commit();
    };
    auto ldgA = [&](int ch, float4& X) {
        X = *(const float4*)(embRow + ch * BK);
    };
    auto stsA = [&](int stage, const float4& X) {
        uint32_t o = stage * STG + A_O + ar * RS + aq * 8;
        uint2 v;
        __half2* v2 = (__half2*)&v;
        v2[0] = __floats2half2_rn(X.x, X.y);
        v2[1] = __floats2half2_rn(X.z, X.w);
        *(uint2*)(sm + o) = v;
    };

    const int CH = EMB_D / BK;       // 8
    issueB(0, 0);
    {
        float4 X;
        ldgA(0, X);
        stsA(0, X);
    }
    for (int ch = 0; ch < CH; ch++) {
        cp_wait0();
        __syncthreads();
        const bool more = (ch + 1 < CH);
        if (more) issueB((ch + 1) & 1, ch + 1);
        float4 X;
        if (more) ldgA(ch + 1, X);
        mma_chunk1(sb + (ch & 1) * STG, lane, warp_n, acc);
        if (more) stsA((ch + 1) & 1, X);
    }

    // store fp16 PQ; fold b1 into the P half (global cols < 512)
    #pragma unroll
    for (int mt = 0; mt < 2; mt++)
        #pragma unroll
        for (int h = 0; h < 2; h++) {
            int r = m0 + mt * 16 + (lane >> 2) + 8 * h;
            if (r < n_nodes) {
                #pragma unroll
                for (int nb = 0; nb < 4; nb++) {
                    int c = n0 + warp_n * 32 + nb * 8 + (lane & 3) * 2;
                    float v0 = acc[mt][nb][2 * h];
                    float v1 = acc[mt][nb][2 * h + 1];
                    if (c < 512) { v0 += b1[c]; v1 += b1[c + 1]; }
                    *(__half2*)(g_PQh + (size_t)r * PQN + c) =
                        __floats2half2_rn(v0, v1);
                }
            }
        }
}

// ---------------- GEMM 2+3: h1 on-the-fly, 1-pass GEMM vs W2, relu, dot W3 ----------------
__global__ __launch_bounds__(NT, 3)
void gemm_l23(const int* __restrict__ edge_index,
              const int* __restrict__ move_idx, int n_edges,
              const float* __restrict__ b2,
              const float* __restrict__ W3, const float* __restrict__ b3,
              float* __restrict__ out, int M)
{
    extern __shared__ char sm[];
    const uint32_t sb = smem_u32(sm);
    const int t = threadIdx.x, lane = t & 31, warp_n = t >> 5;
    const int m0 = blockIdx.x * BM;

    int*   offS = (int*)(sm + AUXO);            // 32 ints
    int*   offT = (int*)(sm + AUXO + 128);      // 32 ints
    float* b2s  = (float*)(sm + AUXO + 256);    // 256 floats
    float* w3s  = (float*)(sm + AUXO + 1280);   // 256 floats
    float* red  = (float*)(sm + AUXO + 2304);   // [32][8] floats

    if (t < 32) {
        int m = m0 + t; if (m >= M) m = M - 1;
        int e = move_idx[m];
        offS[t] = edge_index[e] * PQN;
        offT[t] = edge_index[n_edges + e] * PQN + 512;
    }
    b2s[t] = b2[t];
    w3s[t] = W3[t];
    __syncthreads();

    float acc[2][4][4];
    #pragma unroll
    for (int a = 0; a < 2; a++)
        #pragma unroll
        for (int b = 0; b < 4; b++)
            #pragma unroll
            for (int c = 0; c < 4; c++) acc[a][b][c] = 0.f;

    const int r = t >> 3;            // A row (0..31)
    const int q = t & 7;             // 4-col group within the 32-k chunk
    const int myS = offS[r];
    const int myT = offT[r];

    auto issueB = [&](int stage, int ch) {
        uint32_t sg = sb + stage * STG;
        int k0 = ch * BK;
        #pragma unroll
        for (int i = 0; i < 4; i++) {        // B hi: 1024 cp16
            int g = t + i * NT;
            int row = g >> 2, c = g & 3;
            cp16(sg + BH_O + row * RS + c * 16,
                 g_W2h + (size_t)row * H1DIM + k0 + c * 8);
        }
        cp_commit();
    };
    auto ldgA = [&](int ch, uint2& S, uint2& T) {
        int cb = ch * BK + q * 4;
        S = *(const uint2*)(g_PQh + myS + cb);
        T = *(const uint2*)(g_PQh + myT + cb);
    };
    auto stsA = [&](int stage, const uint2& S, const uint2& T) {
        uint32_t o = stage * STG + A_O + r * RS + q * 8;
        const __half2 z = __floats2half2_rn(0.f, 0.f);
        uint2 v;
        const __half2* s2 = (const __half2*)&S;
        const __half2* t2 = (const __half2*)&T;
        __half2* v2 = (__half2*)&v;
        v2[0] = __hmax2(__hadd2(s2[0], t2[0]), z);
        v2[1] = __hmax2(__hadd2(s2[1], t2[1]), z);
        *(uint2*)(sm + o) = v;
    };

    const int CH = H1DIM / BK;       // 16
    issueB(0, 0);
    {
        uint2 S, T;
        ldgA(0, S, T);
        stsA(0, S, T);
    }
    for (int ch = 0; ch < CH; ch++) {
        cp_wait0();
        __syncthreads();
        const bool more = (ch + 1 < CH);
        if (more) issueB((ch + 1) & 1, ch + 1);
        uint2 S, T;
        if (more) ldgA(ch + 1, S, T);
        mma_chunk1(sb + (ch & 1) * STG, lane, warp_n, acc);
        if (more) stsA((ch + 1) & 1, S, T);
    }

    // epilogue: +b2, relu, dot w3, quad-reduce, smem partials per warp_n
    #pragma unroll
    for (int mt = 0; mt < 2; mt++)
        #pragma unroll
        for (int h = 0; h < 2; h++) {
            int ri = mt * 16 + (lane >> 2) + 8 * h;   // 0..31
            float p = 0.f;
            #pragma unroll
            for (int nb = 0; nb < 4; nb++) {
                int c = warp_n * 32 + nb * 8 + (lane & 3) * 2;
                float v0 = acc[mt][nb][2 * h]     + b2s[c];
                float v1 = acc[mt][nb][2 * h + 1] + b2s[c + 1];
                v0 = v0 > 0.f ? v0 : 0.f;
                v1 = v1 > 0.f ? v1 : 0.f;
                p += v0 * w3s[c] + v1 * w3s[c + 1];
            }
            p += __shfl_xor_sync(0xffffffffu, p, 1);
            p += __shfl_xor_sync(0xffffffffu, p, 2);
            if ((lane & 3) == 0) red[ri * 8 + warp_n] = p;
        }
    __syncthreads();
    if (t < 32) {
        int m = m0 + t;
        if (m < M) {
            float s = b3[0];
            #pragma unroll
            for (int j = 0; j < 8; j++) s += red[t * 8 + j];
            out[m] = s;
        }
    }
}

// ---------------- launch ----------------
extern "C" void kernel_launch(void* const* d_in, const int* in_sizes, int n_in,
                              void* d_out, int out_size)
{
    const float* emb        = (const float*)d_in[0];
    const int*   edge_index = (const int*)d_in[1];
    const int*   move_idx   = (const int*)d_in[2];
    const float* W1 = (const float*)d_in[3];
    const float* b1 = (const float*)d_in[4];
    const float* W2 = (const float*)d_in[5];
    const float* b2 = (const float*)d_in[6];
    const float* W3 = (const float*)d_in[7];
    const float* b3 = (const float*)d_in[8];
    float* out = (float*)d_out;

    int n_nodes = in_sizes[0] / EMB_D;
    int n_edges = in_sizes[1] / 2;
    int M       = in_sizes[2];
    int mtiles  = (M + BM - 1) / BM;
    int ntiles  = (n_nodes + BM - 1) / BM;

    cudaFuncSetAttribute(gemm_pq,  cudaFuncAttributeMaxDynamicSharedMemorySize, SMEM_TOTAL);
    cudaFuncSetAttribute(gemm_l23, cudaFuncAttributeMaxDynamicSharedMemorySize, SMEM_TOTAL);

    prep_w<<<256, 256>>>(W1, W2);
    {
        dim3 grid(PQN / BN, ntiles);     // 4 x 3125
        gemm_pq<<<grid, NT, SMEM_TOTAL>>>(emb, b1, n_nodes);
    }
    gemm_l23<<<mtiles, NT, SMEM_TOTAL>>>(edge_index, move_idx, n_edges,
                                         b2, W3, b3, out, M);
}

// round 16
// speedup vs baseline: 1.1774x; 1.1774x over previous
#include <cuda_runtime.h>
#include <cuda_fp16.h>
#include <cstdint>

// ---------------------------------------------------------------------------
// MovePredictor: logits = W3 . relu(W2 . relu(W1.[e_src;e_tgt] + b1) + b2) + b3
//  - PQ = emb @ [W1_left; W1_right]^T over NODES (b1 folded into P), fp16 out
//  - pq consumes emb fp32 directly; h1 built on the fly in l23
//  - 1-pass fp16 GEMMs; 256-thread CTAs, 2 CTAs/SM, CTA tile 64x256,
//    warp tile 64x32, BK=64, 2-stage cp.async, B-fragment prefetch,
//    single barrier per chunk.
// ---------------------------------------------------------------------------

#define N_NODES_MAX 100000
#define EMB_D   256
#define H1DIM   512
#define H2DIM   256
#define PQN     1024

#define BM 64
#define BN 256
#define BK 64
#define RS 144                   // 128B data + 16B pad
#define NT 256

// stage layout: A (64x144) + B hi (256x144)
#define A_O   0
#define BH_O  9216
#define STG   46080
#define AUXO  (STG * 2)          // 92160
#define SMEM_TOTAL (AUXO + 6144)

// ---- device globals (allocation-free scratch) ----
__device__ __half g_PQh[(size_t)N_NODES_MAX * PQN];
__device__ __half g_W1sh[(size_t)PQN * EMB_D];
__device__ __half g_W2h[(size_t)H2DIM * H1DIM];

// ---------------- helpers ----------------
__device__ __forceinline__ uint32_t smem_u32(const void* p) {
    uint32_t a;
    asm("{ .reg .u64 t; cvta.to.shared.u64 t, %1; cvt.u32.u64 %0, t; }"
        : "=r"(a) : "l"(p));
    return a;
}
__device__ __forceinline__ void cp16(uint32_t dst, const void* src) {
    asm volatile("cp.async.cg.shared.global [%0], [%1], 16;" :: "r"(dst), "l"(src));
}
__device__ __forceinline__ void cp_commit() {
    asm volatile("cp.async.commit_group;" ::: "memory");
}
__device__ __forceinline__ void cp_wait0() {
    asm volatile("cp.async.wait_group 0;" ::: "memory");
}
__device__ __forceinline__ void ldsm_x4(uint32_t* r, uint32_t addr) {
    asm volatile("ldmatrix.sync.aligned.m8n8.x4.shared.b16 {%0,%1,%2,%3}, [%4];"
                 : "=r"(r[0]), "=r"(r[1]), "=r"(r[2]), "=r"(r[3]) : "r"(addr));
}
__device__ __forceinline__ void mma_f16(float* c, const uint32_t* a,
                                        uint32_t b0, uint32_t b1) {
    asm volatile(
        "mma.sync.aligned.m16n8k16.row.col.f32.f16.f16.f32 "
        "{%0,%1,%2,%3}, {%4,%5,%6,%7}, {%8,%9}, {%0,%1,%2,%3};"
        : "+f"(c[0]), "+f"(c[1]), "+f"(c[2]), "+f"(c[3])
        : "r"(a[0]), "r"(a[1]), "r"(a[2]), "r"(a[3]), "r"(b0), "r"(b1));
}

// 64x32 warp tile over one 64-k chunk (4 k16 steps), 1-pass,
// B fragments double-buffered across kt (A loaded at use).
__device__ __forceinline__ void mma_chunk1(uint32_t stg, int lane, int warp_n,
                                           float acc[4][4][4]) {
    const uint32_t aB = stg + A_O  + (lane & 15) * RS + (lane >> 4) * 16;
    const uint32_t bB = stg + BH_O + (warp_n * 32 + (lane & 15)) * RS + (lane >> 4) * 16;
    uint32_t b0[2][4], b1[2][4];
    ldsm_x4(b0[0], bB);
    ldsm_x4(b0[1], bB + 16 * RS);
    #pragma unroll
    for (int kt = 0; kt < 4; kt++) {
        uint32_t (*bc)[4] = (kt & 1) ? b1 : b0;
        uint32_t (*bn)[4] = (kt & 1) ? b0 : b1;
        // A fragments for this kt
        uint32_t aR[4][4];
        #pragma unroll
        for (int mt = 0; mt < 4; mt++)
            ldsm_x4(aR[mt], aB + mt * 16 * RS + kt * 32);
        // prefetch next kt's B before the MMA block
        if (kt < 3) {
            ldsm_x4(bn[0], bB + (kt + 1) * 32);
            ldsm_x4(bn[1], bB + 16 * RS + (kt + 1) * 32);
        }
        #pragma unroll
        for (int mt = 0; mt < 4; mt++)
            #pragma unroll
            for (int nb = 0; nb < 2; nb++) {
                mma_f16(acc[mt][2 * nb],     aR[mt], bc[nb][0], bc[nb][2]);
                mma_f16(acc[mt][2 * nb + 1], aR[mt], bc[nb][1], bc[nb][3]);
            }
    }
}

// ---------------- prep: weights only ----------------
__global__ void prep_w(const float* __restrict__ W1, const float* __restrict__ W2)
{
    int total = PQN * EMB_D + H2DIM * H1DIM;     // 393216
    for (int i = blockIdx.x * blockDim.x + threadIdx.x; i < total;
         i += gridDim.x * blockDim.x) {
        if (i < PQN * EMB_D) {
            int r = i >> 8, k = i & 255;
            g_W1sh[i] = __float2half_rn(
                W1[(size_t)(r & 511) * 512 + k + ((r >> 9) << 8)]);
        } else {
            int j = i - PQN * EMB_D;
            g_W2h[j] = __float2half_rn(W2[j]);
        }
    }
}

// ---------------- GEMM 1: PQ = emb @ W1s^T (+b1 on P half), fp16 out ----------------
__global__ __launch_bounds__(NT, 2)
void gemm_pq(const float* __restrict__ emb, const float* __restrict__ b1,
             int n_nodes)
{
    extern __shared__ char sm[];
    const uint32_t sb = smem_u32(sm);
    const int t = threadIdx.x, lane = t & 31, warp_n = t >> 5;
    const int m0 = blockIdx.y * BM;
    const int n0 = blockIdx.x * BN;

    float acc[4][4][4];
    #pragma unroll
    for (int a = 0; a < 4; a++)
        #pragma unroll
        for (int b = 0; b < 4; b++)
            #pragma unroll
            for (int c = 0; c < 4; c++) acc[a][b][c] = 0.f;

    // A path: 64 rows x 4 col-groups -> per-thread 16 fp32 LDG, cvt, 2x16B STS
    const int ar = t >> 2;           // A row (0..63)
    const int aq = t & 3;            // 16-col group of 64
    int gm = m0 + ar; if (gm >= n_nodes) gm = n_nodes - 1;
    const float* embRow = emb + (size_t)gm * EMB_D + aq * 16;

    auto issueB = [&](int stage, int ch) {
        uint32_t sg = sb + stage * STG;
        int k0 = ch * BK;
        #pragma unroll
        for (int i = 0; i < 8; i++) {        // B hi: 2048 cp16
            int g = t + i * NT;
            int row = g >> 3, c = g & 7;
            cp16(sg + BH_O + row * RS + c * 16,
                 g_W1sh + (size_t)(n0 + row) * EMB_D + k0 + c * 8);
        }
        cp_commit();
    };
    auto ldgA = [&](int ch, float4* X) {
        const float* p = embRow + ch * BK;
        #pragma unroll
        for (int j = 0; j < 4; j++) X[j] = *(const float4*)(p + 4 * j);
    };
    auto stsA = [&](int stage, const float4* X) {
        uint32_t o = stage * STG + A_O + ar * RS + aq * 32;
        uint4 v0, v1;
        __half2* a2 = (__half2*)&v0;
        __half2* b2v = (__half2*)&v1;
        a2[0]  = __floats2half2_rn(X[0].x, X[0].y);
        a2[1]  = __floats2half2_rn(X[0].z, X[0].w);
        a2[2]  = __floats2half2_rn(X[1].x, X[1].y);
        a2[3]  = __floats2half2_rn(X[1].z, X[1].w);
        b2v[0] = __floats2half2_rn(X[2].x, X[2].y);
        b2v[1] = __floats2half2_rn(X[2].z, X[2].w);
        b2v[2] = __floats2half2_rn(X[3].x, X[3].y);
        b2v[3] = __floats2half2_rn(X[3].z, X[3].w);
        *(uint4*)(sm + o)      = v0;
        *(uint4*)(sm + o + 16) = v1;
    };

    const int CH = EMB_D / BK;       // 4
    issueB(0, 0);
    {
        float4 X[4];
        ldgA(0, X);
        stsA(0, X);
    }
    for (int ch = 0; ch < CH; ch++) {
        cp_wait0();
        __syncthreads();
        const bool more = (ch + 1 < CH);
        if (more) issueB((ch + 1) & 1, ch + 1);
        float4 X[4];
        if (more) ldgA(ch + 1, X);
        mma_chunk1(sb + (ch & 1) * STG, lane, warp_n, acc);
        if (more) stsA((ch + 1) & 1, X);
    }

    // store fp16 PQ; fold b1 into the P half (global cols < 512)
    #pragma unroll
    for (int mt = 0; mt < 4; mt++)
        #pragma unroll
        for (int h = 0; h < 2; h++) {
            int r = m0 + mt * 16 + (lane >> 2) + 8 * h;
            if (r < n_nodes) {
                #pragma unroll
                for (int nb = 0; nb < 4; nb++) {
                    int c = n0 + warp_n * 32 + nb * 8 + (lane & 3) * 2;
                    float v0 = acc[mt][nb][2 * h];
                    float v1 = acc[mt][nb][2 * h + 1];
                    if (c < 512) { v0 += b1[c]; v1 += b1[c + 1]; }
                    *(__half2*)(g_PQh + (size_t)r * PQN + c) =
                        __floats2half2_rn(v0, v1);
                }
            }
        }
}

// ---------------- GEMM 2+3: h1 on-the-fly, 1-pass GEMM vs W2, relu, dot W3 ----------------
__global__ __launch_bounds__(NT, 2)
void gemm_l23(const int* __restrict__ edge_index,
              const int* __restrict__ move_idx, int n_edges,
              const float* __restrict__ b2,
              const float* __restrict__ W3, const float* __restrict__ b3,
              float* __restrict__ out, int M)
{
    extern __shared__ char sm[];
    const uint32_t sb = smem_u32(sm);
    const int t = threadIdx.x, lane = t & 31, warp_n = t >> 5;
    const int m0 = blockIdx.x * BM;

    int*   offS = (int*)(sm + AUXO);            // 64 ints
    int*   offT = (int*)(sm + AUXO + 256);      // 64 ints
    float* b2s  = (float*)(sm + AUXO + 512);    // 256 floats
    float* w3s  = (float*)(sm + AUXO + 1536);   // 256 floats
    float* red  = (float*)(sm + AUXO + 2560);   // [64][8] floats

    if (t < 64) {
        int m = m0 + t; if (m >= M) m = M - 1;
        int e = move_idx[m];
        offS[t] = edge_index[e] * PQN;
        offT[t] = edge_index[n_edges + e] * PQN + 512;
    }
    b2s[t] = b2[t];
    w3s[t] = W3[t];
    __syncthreads();

    float acc[4][4][4];
    #pragma unroll
    for (int a = 0; a < 4; a++)
        #pragma unroll
        for (int b = 0; b < 4; b++)
            #pragma unroll
            for (int c = 0; c < 4; c++) acc[a][b][c] = 0.f;

    const int r = t >> 2;            // A row (0..63)
    const int q = t & 3;             // 16-col group within the 64-k chunk
    const int myS = offS[r];
    const int myT = offT[r];

    auto issueB = [&](int stage, int ch) {
        uint32_t sg = sb + stage * STG;
        int k0 = ch * BK;
        #pragma unroll
        for (int i = 0; i < 8; i++) {        // B hi: 2048 cp16
            int g = t + i * NT;
            int row = g >> 3, c = g & 7;
            cp16(sg + BH_O + row * RS + c * 16,
                 g_W2h + (size_t)row * H1DIM + k0 + c * 8);
        }
        cp_commit();
    };
    auto ldgA = [&](int ch, uint4* S, uint4* T) {
        int cb = ch * BK + q * 16;
        const __half* ps = g_PQh + myS + cb;
        const __half* pt = g_PQh + myT + cb;
        S[0] = *(const uint4*)ps;
        S[1] = *(const uint4*)(ps + 8);
        T[0] = *(const uint4*)pt;
        T[1] = *(const uint4*)(pt + 8);
    };
    auto stsA = [&](int stage, const uint4* S, const uint4* T) {
        uint32_t o = stage * STG + A_O + r * RS + q * 32;
        const __half2 z = __floats2half2_rn(0.f, 0.f);
        #pragma unroll
        for (int j = 0; j < 2; j++) {
            uint4 v;
            const __half2* s2 = (const __half2*)&S[j];
            const __half2* t2 = (const __half2*)&T[j];
            __half2* v2 = (__half2*)&v;
            #pragma unroll
            for (int k = 0; k < 4; k++)
                v2[k] = __hmax2(__hadd2(s2[k], t2[k]), z);
            *(uint4*)(sm + o + j * 16) = v;
        }
    };

    const int CH = H1DIM / BK;       // 8
    issueB(0, 0);
    {
        uint4 S[2], T[2];
        ldgA(0, S, T);
        stsA(0, S, T);
    }
    for (int ch = 0; ch < CH; ch++) {
        cp_wait0();
        __syncthreads();
        const bool more = (ch + 1 < CH);
        if (more) issueB((ch + 1) & 1, ch + 1);
        uint4 S[2], T[2];
        if (more) ldgA(ch + 1, S, T);
        mma_chunk1(sb + (ch & 1) * STG, lane, warp_n, acc);
        if (more) stsA((ch + 1) & 1, S, T);
    }

    // epilogue: +b2, relu, dot w3, quad-reduce, smem partials per warp_n
    #pragma unroll
    for (int mt = 0; mt < 4; mt++)
        #pragma unroll
        for (int h = 0; h < 2; h++) {
            int ri = mt * 16 + (lane >> 2) + 8 * h;   // 0..63
            float p = 0.f;
            #pragma unroll
            for (int nb = 0; nb < 4; nb++) {
                int c = warp_n * 32 + nb * 8 + (lane & 3) * 2;
                float v0 = acc[mt][nb][2 * h]     + b2s[c];
                float v1 = acc[mt][nb][2 * h + 1] + b2s[c + 1];
                v0 = v0 > 0.f ? v0 : 0.f;
                v1 = v1 > 0.f ? v1 : 0.f;
                p += v0 * w3s[c] + v1 * w3s[c + 1];
            }
            p += __shfl_xor_sync(0xffffffffu, p, 1);
            p += __shfl_xor_sync(0xffffffffu, p, 2);
            if ((lane & 3) == 0) red[ri * 8 + warp_n] = p;
        }
    __syncthreads();
    if (t < 64) {
        int m = m0 + t;
        if (m < M) {
            float s = b3[0];
            #pragma unroll
            for (int j = 0; j < 8; j++) s += red[t * 8 + j];
            out[m] = s;
        }
    }
}

// ---------------- launch ----------------
extern "C" void kernel_launch(void* const* d_in, const int* in_sizes, int n_in,
                              void* d_out, int out_size)
{
    const float* emb        = (const float*)d_in[0];
    const int*   edge_index = (const int*)d_in[1];
    const int*   move_idx   = (const int*)d_in[2];
    const float* W1 = (const float*)d_in[3];
    const float* b1 = (const float*)d_in[4];
    const float* W2 = (const float*)d_in[5];
    const float* b2 = (const float*)d_in[6];
    const float* W3 = (const float*)d_in[7];
    const float* b3 = (const float*)d_in[8];
    float* out = (float*)d_out;

    int n_nodes = in_sizes[0] / EMB_D;
    int n_edges = in_sizes[1] / 2;
    int M       = in_sizes[2];
    int mtiles  = (M + BM - 1) / BM;
    int ntiles  = (n_nodes + BM - 1) / BM;

    cudaFuncSetAttribute(gemm_pq,  cudaFuncAttributeMaxDynamicSharedMemorySize, SMEM_TOTAL);
    cudaFuncSetAttribute(gemm_l23, cudaFuncAttributeMaxDynamicSharedMemorySize, SMEM_TOTAL);

    prep_w<<<256, 256>>>(W1, W2);
    {
        dim3 grid(PQN / BN, ntiles);     // 4 x 1563
        gemm_pq<<<grid, NT, SMEM_TOTAL>>>(emb, b1, n_nodes);
    }
    gemm_l23<<<mtiles, NT, SMEM_TOTAL>>>(edge_index, move_idx, n_edges,
                                         b2, W3, b3, out, M);
}

// round 17
// speedup vs baseline: 1.2727x; 1.0809x over previous
#include <cuda_runtime.h>
#include <cuda_fp16.h>
#include <cstdint>

// ---------------------------------------------------------------------------
// MovePredictor: logits = W3 . relu(W2 . relu(W1.[e_src;e_tgt] + b1) + b2) + b3
//  - PQ = emb @ [W1_left; W1_right]^T over NODES (b1 folded into P), fp16 out
//  - pq consumes emb fp32 directly; h1 built on the fly in l23
//  - 1-pass fp16 GEMMs; 256-thread CTAs, 2 CTAs/SM, CTA tile 64x256,
//    warp tile 64x32, BK=64, 2-stage cp.async, gather hoisted above waits.
// ---------------------------------------------------------------------------

#define N_NODES_MAX 100000
#define EMB_D   256
#define H1DIM   512
#define H2DIM   256
#define PQN     1024

#define BM 64
#define BN 256
#define BK 64
#define RS 144                   // 128B data + 16B pad
#define NT 256

// stage layout: A (64x144) + B hi (256x144)
#define A_O   0
#define BH_O  9216
#define STG   46080
#define AUXO  (STG * 2)          // 92160
#define SMEM_TOTAL (AUXO + 6144)

// ---- device globals (allocation-free scratch) ----
__device__ __half g_PQh[(size_t)N_NODES_MAX * PQN];
__device__ __half g_W1sh[(size_t)PQN * EMB_D];
__device__ __half g_W2h[(size_t)H2DIM * H1DIM];

// ---------------- helpers ----------------
__device__ __forceinline__ uint32_t smem_u32(const void* p) {
    uint32_t a;
    asm("{ .reg .u64 t; cvta.to.shared.u64 t, %1; cvt.u32.u64 %0, t; }"
        : "=r"(a) : "l"(p));
    return a;
}
__device__ __forceinline__ void cp16(uint32_t dst, const void* src) {
    asm volatile("cp.async.cg.shared.global [%0], [%1], 16;" :: "r"(dst), "l"(src));
}
__device__ __forceinline__ void cp_commit() {
    asm volatile("cp.async.commit_group;" ::: "memory");
}
__device__ __forceinline__ void cp_wait0() {
    asm volatile("cp.async.wait_group 0;" ::: "memory");
}
__device__ __forceinline__ void ldsm_x4(uint32_t* r, uint32_t addr) {
    asm volatile("ldmatrix.sync.aligned.m8n8.x4.shared.b16 {%0,%1,%2,%3}, [%4];"
                 : "=r"(r[0]), "=r"(r[1]), "=r"(r[2]), "=r"(r[3]) : "r"(addr));
}
__device__ __forceinline__ void mma_f16(float* c, const uint32_t* a,
                                        uint32_t b0, uint32_t b1) {
    asm volatile(
        "mma.sync.aligned.m16n8k16.row.col.f32.f16.f16.f32 "
        "{%0,%1,%2,%3}, {%4,%5,%6,%7}, {%8,%9}, {%0,%1,%2,%3};"
        : "+f"(c[0]), "+f"(c[1]), "+f"(c[2]), "+f"(c[3])
        : "r"(a[0]), "r"(a[1]), "r"(a[2]), "r"(a[3]), "r"(b0), "r"(b1));
}

// 64x32 warp tile over one 64-k chunk (4 k16 steps), 1-pass (R14 version)
__device__ __forceinline__ void mma_chunk1(uint32_t stg, int lane, int warp_n,
                                           float acc[4][4][4]) {
    const uint32_t aB = stg + A_O  + (lane & 15) * RS + (lane >> 4) * 16;
    const uint32_t bB = stg + BH_O + (warp_n * 32 + (lane & 15)) * RS + (lane >> 4) * 16;
    #pragma unroll
    for (int kt = 0; kt < 4; kt++) {
        uint32_t aR[4][4], bH[2][4];
        #pragma unroll
        for (int mt = 0; mt < 4; mt++)
            ldsm_x4(aR[mt], aB + mt * 16 * RS + kt * 32);
        #pragma unroll
        for (int nb = 0; nb < 2; nb++)
            ldsm_x4(bH[nb], bB + nb * 16 * RS + kt * 32);
        #pragma unroll
        for (int mt = 0; mt < 4; mt++)
            #pragma unroll
            for (int nb = 0; nb < 2; nb++) {
                mma_f16(acc[mt][2 * nb],     aR[mt], bH[nb][0], bH[nb][2]);
                mma_f16(acc[mt][2 * nb + 1], aR[mt], bH[nb][1], bH[nb][3]);
            }
    }
}

// ---------------- prep: weights only ----------------
__global__ void prep_w(const float* __restrict__ W1, const float* __restrict__ W2)
{
    int total = PQN * EMB_D + H2DIM * H1DIM;     // 393216
    for (int i = blockIdx.x * blockDim.x + threadIdx.x; i < total;
         i += gridDim.x * blockDim.x) {
        if (i < PQN * EMB_D) {
            int r = i >> 8, k = i & 255;
            g_W1sh[i] = __float2half_rn(
                W1[(size_t)(r & 511) * 512 + k + ((r >> 9) << 8)]);
        } else {
            int j = i - PQN * EMB_D;
            g_W2h[j] = __float2half_rn(W2[j]);
        }
    }
}

// ---------------- GEMM 1: PQ = emb @ W1s^T (+b1 on P half), fp16 out ----------------
__global__ __launch_bounds__(NT, 2)
void gemm_pq(const float* __restrict__ emb, const float* __restrict__ b1,
             int n_nodes)
{
    extern __shared__ char sm[];
    const uint32_t sb = smem_u32(sm);
    const int t = threadIdx.x, lane = t & 31, warp_n = t >> 5;
    const int m0 = blockIdx.y * BM;
    const int n0 = blockIdx.x * BN;

    float acc[4][4][4];
    #pragma unroll
    for (int a = 0; a < 4; a++)
        #pragma unroll
        for (int b = 0; b < 4; b++)
            #pragma unroll
            for (int c = 0; c < 4; c++) acc[a][b][c] = 0.f;

    // A path: 64 rows x 4 col-groups -> per-thread 16 fp32 LDG, cvt, 2x16B STS
    const int ar = t >> 2;           // A row (0..63)
    const int aq = t & 3;            // 16-col group of 64
    int gm = m0 + ar; if (gm >= n_nodes) gm = n_nodes - 1;
    const float* embRow = emb + (size_t)gm * EMB_D + aq * 16;

    auto issueB = [&](int stage, int ch) {
        uint32_t sg = sb + stage * STG;
        int k0 = ch * BK;
        #pragma unroll
        for (int i = 0; i < 8; i++) {        // B hi: 2048 cp16
            int g = t + i * NT;
            int row = g >> 3, c = g & 7;
            cp16(sg + BH_O + row * RS + c * 16,
                 g_W1sh + (size_t)(n0 + row) * EMB_D + k0 + c * 8);
        }
        cp_commit();
    };
    auto ldgA = [&](int ch, float4* X) {
        const float* p = embRow + ch * BK;
        #pragma unroll
        for (int j = 0; j < 4; j++) X[j] = *(const float4*)(p + 4 * j);
    };
    auto stsA = [&](int stage, const float4* X) {
        uint32_t o = stage * STG + A_O + ar * RS + aq * 32;
        uint4 v0, v1;
        __half2* a2 = (__half2*)&v0;
        __half2* b2v = (__half2*)&v1;
        a2[0]  = __floats2half2_rn(X[0].x, X[0].y);
        a2[1]  = __floats2half2_rn(X[0].z, X[0].w);
        a2[2]  = __floats2half2_rn(X[1].x, X[1].y);
        a2[3]  = __floats2half2_rn(X[1].z, X[1].w);
        b2v[0] = __floats2half2_rn(X[2].x, X[2].y);
        b2v[1] = __floats2half2_rn(X[2].z, X[2].w);
        b2v[2] = __floats2half2_rn(X[3].x, X[3].y);
        b2v[3] = __floats2half2_rn(X[3].z, X[3].w);
        *(uint4*)(sm + o)      = v0;
        *(uint4*)(sm + o + 16) = v1;
    };

    const int CH = EMB_D / BK;       // 4
    issueB(0, 0);
    {
        float4 X[4];
        ldgA(0, X);
        stsA(0, X);
    }
    for (int ch = 0; ch < CH; ch++) {
        const bool more = (ch + 1 < CH);
        float4 X[4];
        if (more) ldgA(ch + 1, X);       // hoisted: LDG in flight during wait
        cp_wait0();
        __syncthreads();
        if (more) issueB((ch + 1) & 1, ch + 1);
        mma_chunk1(sb + (ch & 1) * STG, lane, warp_n, acc);
        if (more) stsA((ch + 1) & 1, X);
    }

    // store fp16 PQ; fold b1 into the P half (global cols < 512)
    #pragma unroll
    for (int mt = 0; mt < 4; mt++)
        #pragma unroll
        for (int h = 0; h < 2; h++) {
            int r = m0 + mt * 16 + (lane >> 2) + 8 * h;
            if (r < n_nodes) {
                #pragma unroll
                for (int nb = 0; nb < 4; nb++) {
                    int c = n0 + warp_n * 32 + nb * 8 + (lane & 3) * 2;
                    float v0 = acc[mt][nb][2 * h];
                    float v1 = acc[mt][nb][2 * h + 1];
                    if (c < 512) { v0 += b1[c]; v1 += b1[c + 1]; }
                    *(__half2*)(g_PQh + (size_t)r * PQN + c) =
                        __floats2half2_rn(v0, v1);
                }
            }
        }
}

// ---------------- GEMM 2+3: h1 on-the-fly, 1-pass GEMM vs W2, relu, dot W3 ----------------
__global__ __launch_bounds__(NT, 2)
void gemm_l23(const int* __restrict__ edge_index,
              const int* __restrict__ move_idx, int n_edges,
              const float* __restrict__ b2,
              const float* __restrict__ W3, const float* __restrict__ b3,
              float* __restrict__ out, int M)
{
    extern __shared__ char sm[];
    const uint32_t sb = smem_u32(sm);
    const int t = threadIdx.x, lane = t & 31, warp_n = t >> 5;
    const int m0 = blockIdx.x * BM;

    int*   offS = (int*)(sm + AUXO);            // 64 ints
    int*   offT = (int*)(sm + AUXO + 256);      // 64 ints
    float* b2s  = (float*)(sm + AUXO + 512);    // 256 floats
    float* w3s  = (float*)(sm + AUXO + 1536);   // 256 floats
    float* red  = (float*)(sm + AUXO + 2560);   // [64][8] floats

    if (t < 64) {
        int m = m0 + t; if (m >= M) m = M - 1;
        int e = move_idx[m];
        offS[t] = edge_index[e] * PQN;
        offT[t] = edge_index[n_edges + e] * PQN + 512;
    }
    b2s[t] = b2[t];
    w3s[t] = W3[t];
    __syncthreads();

    float acc[4][4][4];
    #pragma unroll
    for (int a = 0; a < 4; a++)
        #pragma unroll
        for (int b = 0; b < 4; b++)
            #pragma unroll
            for (int c = 0; c < 4; c++) acc[a][b][c] = 0.f;

    const int r = t >> 2;            // A row (0..63)
    const int q = t & 3;             // 16-col group within the 64-k chunk
    const int myS = offS[r];
    const int myT = offT[r];

    auto issueB = [&](int stage, int ch) {
        uint32_t sg = sb + stage * STG;
        int k0 = ch * BK;
        #pragma unroll
        for (int i = 0; i < 8; i++) {        // B hi: 2048 cp16
            int g = t + i * NT;
            int row = g >> 3, c = g & 7;
            cp16(sg + BH_O + row * RS + c * 16,
                 g_W2h + (size_t)row * H1DIM + k0 + c * 8);
        }
        cp_commit();
    };
    auto ldgA = [&](int ch, uint4* S, uint4* T) {
        int cb = ch * BK + q * 16;
        const __half* ps = g_PQh + myS + cb;
        const __half* pt = g_PQh + myT + cb;
        S[0] = *(const uint4*)ps;
        S[1] = *(const uint4*)(ps + 8);
        T[0] = *(const uint4*)pt;
        T[1] = *(const uint4*)(pt + 8);
    };
    auto stsA = [&](int stage, const uint4* S, const uint4* T) {
        uint32_t o = stage * STG + A_O + r * RS + q * 32;
        const __half2 z = __floats2half2_rn(0.f, 0.f);
        #pragma unroll
        for (int j = 0; j < 2; j++) {
            uint4 v;
            const __half2* s2 = (const __half2*)&S[j];
            const __half2* t2 = (const __half2*)&T[j];
            __half2* v2 = (__half2*)&v;
            #pragma unroll
            for (int k = 0; k < 4; k++)
                v2[k] = __hmax2(__hadd2(s2[k], t2[k]), z);
            *(uint4*)(sm + o + j * 16) = v;
        }
    };

    const int CH = H1DIM / BK;       // 8
    issueB(0, 0);
    {
        uint4 S[2], T[2];
        ldgA(0, S, T);
        stsA(0, S, T);
    }
    for (int ch = 0; ch < CH; ch++) {
        const bool more = (ch + 1 < CH);
        uint4 S[2], T[2];
        if (more) ldgA(ch + 1, S, T);    // hoisted: gather in flight during wait
        cp_wait0();
        __syncthreads();
        if (more) issueB((ch + 1) & 1, ch + 1);
        mma_chunk1(sb + (ch & 1) * STG, lane, warp_n, acc);
        if (more) stsA((ch + 1) & 1, S, T);
    }

    // epilogue: +b2, relu, dot w3, quad-reduce, smem partials per warp_n
    #pragma unroll
    for (int mt = 0; mt < 4; mt++)
        #pragma unroll
        for (int h = 0; h < 2; h++) {
            int ri = mt * 16 + (lane >> 2) + 8 * h;   // 0..63
            float p = 0.f;
            #pragma unroll
            for (int nb = 0; nb < 4; nb++) {
                int c = warp_n * 32 + nb * 8 + (lane & 3) * 2;
                float v0 = acc[mt][nb][2 * h]     + b2s[c];
                float v1 = acc[mt][nb][2 * h + 1] + b2s[c + 1];
                v0 = v0 > 0.f ? v0 : 0.f;
                v1 = v1 > 0.f ? v1 : 0.f;
                p += v0 * w3s[c] + v1 * w3s[c + 1];
            }
            p += __shfl_xor_sync(0xffffffffu, p, 1);
            p += __shfl_xor_sync(0xffffffffu, p, 2);
            if ((lane & 3) == 0) red[ri * 8 + warp_n] = p;
        }
    __syncthreads();
    if (t < 64) {
        int m = m0 + t;
        if (m < M) {
            float s = b3[0];
            #pragma unroll
            for (int j = 0; j < 8; j++) s += red[t * 8 + j];
            out[m] = s;
        }
    }
}

// ---------------- launch ----------------
extern "C" void kernel_launch(void* const* d_in, const int* in_sizes, int n_in,
                              void* d_out, int out_size)
{
    const float* emb        = (const float*)d_in[0];
    const int*   edge_index = (const int*)d_in[1];
    const int*   move_idx   = (const int*)d_in[2];
    const float* W1 = (const float*)d_in[3];
    const float* b1 = (const float*)d_in[4];
    const float* W2 = (const float*)d_in[5];
    const float* b2 = (const float*)d_in[6];
    const float* W3 = (const float*)d_in[7];
    const float* b3 = (const float*)d_in[8];
    float* out = (float*)d_out;

    int n_nodes = in_sizes[0] / EMB_D;
    int n_edges = in_sizes[1] / 2;
    int M       = in_sizes[2];
    int mtiles  = (M + BM - 1) / BM;
    int ntiles  = (n_nodes + BM - 1) / BM;

    cudaFuncSetAttribute(gemm_pq,  cudaFuncAttributeMaxDynamicSharedMemorySize, SMEM_TOTAL);
    cudaFuncSetAttribute(gemm_l23, cudaFuncAttributeMaxDynamicSharedMemorySize, SMEM_TOTAL);

    prep_w<<<256, 256>>>(W1, W2);
    {
        dim3 grid(PQN / BN, ntiles);     // 4 x 1563
        gemm_pq<<<grid, NT, SMEM_TOTAL>>>(emb, b1, n_nodes);
    }
    gemm_l23<<<mtiles, NT, SMEM_TOTAL>>>(edge_index, move_idx, n_edges,
                                         b2, W3, b3, out, M);
}